// round 14
// baseline (speedup 1.0000x reference)
#include <cuda_runtime.h>
#include <cuda_fp16.h>
#include <cstdint>

// Problem constants
#define NB  4
#define CCH 256
#define LF  4096
#define L2  1024
#define HH  4
#define EE  64

// ---------------- device scratch (static; no cudaMalloc) ----------------
__device__ __half d_xh   [NB * CCH * LF];
__device__ __half d_xaggh[NB * CCH * L2];
__device__ __half d_qh   [NB * HH * LF * EE];  // [n][h][l][e], log2e*0.125*(Wq x + bq)
__device__ __half d_kh   [NB * HH * L2 * EE];  // [n][h][m][e]
__device__ __half d_vh   [NB * HH * EE * L2];  // [n][h][e][m]
__device__ __half d_oh   [NB * CCH * LF];
__device__ __half d_wqh[CCH * CCH], d_woh[CCH * CCH];
__device__ __half d_wke[CCH * CCH], d_wve[CCH * CCH];   // folded K/V weights (fp16)
__device__ float  d_bke[CCH], d_bve[CCH];               // folded K/V biases (fp32)

// ---------------- prep: x->fp16 + pooling; Wq/Wo->fp16 ----------------
// grid 1088 x 256: blocks [0,1024) one (n,c) row each; [1024,1088) Wq/Wo conversion.
__global__ void prep_kernel(const float* __restrict__ x,
                            const float* __restrict__ wq, const float* __restrict__ wo) {
    int b = blockIdx.x;
    int tid = threadIdx.x;
    if (b < NB * CCH) {
        const float4* xr = reinterpret_cast<const float4*>(x + (long)b * LF);
        __half2* xo = reinterpret_cast<__half2*>(d_xh) + (long)b * (LF / 2);
        __half*  ao = d_xaggh + (long)b * L2;
#pragma unroll
        for (int k = 0; k < 4; k++) {
            int j = tid + k * 256;
            float4 t = xr[j];
            xo[2 * j]     = __floats2half2_rn(t.x, t.y);
            xo[2 * j + 1] = __floats2half2_rn(t.z, t.w);
            float mx = fmaxf(fmaxf(t.x, t.y), fmaxf(t.z, t.w));
            ao[j] = __float2half_rn(0.25f * (t.x + t.y + t.z + t.w) + mx);
        }
    } else {
        const float* src[2] = {wq, wo};
        __half* dst[2] = {d_wqh, d_woh};
#pragma unroll
        for (int k = 0; k < 2; k++) {
            int idx = (b - NB * CCH) * 512 + k * 256 + tid;   // float4 idx in [0, 32768)
            int m = idx >> 14;
            int j = idx & 16383;
            float4 t = reinterpret_cast<const float4*>(src[m])[j];
            __half2* o = reinterpret_cast<__half2*>(dst[m]);
            o[2 * j]     = __floats2half2_rn(t.x, t.y);
            o[2 * j + 1] = __floats2half2_rn(t.z, t.w);
        }
    }
}

// ---------------- weight folding: Weff = W * diag(s) * Wa ; beff = W*t + b ----------------
// s/t are the two stacked eval-BN affines. grid (4,4,2) x 256 (16x16 threads, 4x4 outputs each).
__global__ void wfold_kernel(const float* __restrict__ Wk, const float* __restrict__ Wv,
                             const float* __restrict__ Wa,
                             const float* __restrict__ bk, const float* __restrict__ bv,
                             const float* __restrict__ g1, const float* __restrict__ b1,
                             const float* __restrict__ m1, const float* __restrict__ v1,
                             const float* __restrict__ g2, const float* __restrict__ b2,
                             const float* __restrict__ m2, const float* __restrict__ v2) {
    __shared__ float sA[64][33];
    __shared__ float sB[32][65];
    __shared__ float sS[32];

    const int zk = blockIdx.z;
    const float* W = zk ? Wv : Wk;
    const float* bb = zk ? bv : bk;
    __half* Wout = zk ? d_wve : d_wke;
    float*  bout = zk ? d_bve : d_bke;

    const int tid = threadIdx.x;
    const int tx = tid & 15, ty = tid >> 4;
    const int r0 = blockIdx.y * 64, c0 = blockIdx.x * 64;

    float acc[4][4];
#pragma unroll
    for (int i = 0; i < 4; i++)
#pragma unroll
        for (int j = 0; j < 4; j++) acc[i][j] = 0.0f;

    for (int k0 = 0; k0 < CCH; k0 += 32) {
        if (tid < 32) {
            int k = k0 + tid;
            float i1 = g1[k] * rsqrtf(v1[k] + 1e-5f);
            float i2 = g2[k] * rsqrtf(v2[k] + 1e-5f);
            sS[tid] = i1 * i2;
        }
        __syncthreads();
        for (int i = tid; i < 64 * 32; i += 256) {
            int r = i >> 5, k = i & 31;
            sA[r][k] = W[(long)(r0 + r) * CCH + k0 + k];
        }
        for (int i = tid; i < 32 * 64; i += 256) {
            int k = i >> 6, c = i & 63;
            sB[k][c] = sS[k] * Wa[(long)(k0 + k) * CCH + c0 + c];
        }
        __syncthreads();
#pragma unroll
        for (int kk = 0; kk < 32; kk++) {
            float a[4], bq[4];
#pragma unroll
            for (int i = 0; i < 4; i++) a[i] = sA[ty + 16 * i][kk];
#pragma unroll
            for (int j = 0; j < 4; j++) bq[j] = sB[kk][tx + 16 * j];
#pragma unroll
            for (int i = 0; i < 4; i++)
#pragma unroll
                for (int j = 0; j < 4; j++) acc[i][j] = fmaf(a[i], bq[j], acc[i][j]);
        }
        __syncthreads();
    }
#pragma unroll
    for (int i = 0; i < 4; i++)
#pragma unroll
        for (int j = 0; j < 4; j++)
            Wout[(long)(r0 + ty + 16 * i) * CCH + c0 + tx + 16 * j] =
                __float2half_rn(acc[i][j]);

    // folded bias (once per row-block; 64 rows by threads 0..63)
    if (blockIdx.x == 0 && tid < 64) {
        int r = r0 + tid;
        float s = 0.0f;
        for (int k = 0; k < CCH; k++) {
            float i1 = g1[k] * rsqrtf(v1[k] + 1e-5f);
            float i2 = g2[k] * rsqrtf(v2[k] + 1e-5f);
            float t = (b1[k] - m1[k] * i1) * i2 + (b2[k] - m2[k] * i2);
            s = fmaf(W[(long)r * CCH + k], t, s);
        }
        bout[r] = s + bb[r];
    }
}

// ---------------- helpers ----------------
__device__ __forceinline__ void mma_f16(float4& c, uint32_t a0, uint32_t a1, uint32_t a2,
                                        uint32_t a3, uint32_t b0, uint32_t b1) {
    asm volatile(
        "mma.sync.aligned.m16n8k16.row.col.f32.f16.f16.f32 "
        "{%0,%1,%2,%3}, {%4,%5,%6,%7}, {%8,%9}, {%0,%1,%2,%3};\n"
        : "+f"(c.x), "+f"(c.y), "+f"(c.z), "+f"(c.w)
        : "r"(a0), "r"(a1), "r"(a2), "r"(a3), "r"(b0), "r"(b1));
}
__device__ __forceinline__ uint32_t h2pack(float a, float b) {
    __half2 h = __floats2half2_rn(a, b);
    return *reinterpret_cast<uint32_t*>(&h);
}
__device__ __forceinline__ uint32_t ex2h2(uint32_t in) {
    uint32_t r;
    asm("ex2.approx.f16x2 %0, %1;" : "=r"(r) : "r"(in));
    return r;
}
__device__ __forceinline__ uint32_t stou(const void* p) {
    return (uint32_t)__cvta_generic_to_shared(p);
}
__device__ __forceinline__ void cpa16(uint32_t dst, const void* src) {
    asm volatile("cp.async.cg.shared.global [%0], [%1], 16;\n" :: "r"(dst), "l"(src));
}
__device__ __forceinline__ void cp_commit() { asm volatile("cp.async.commit_group;\n"); }
template <int N> __device__ __forceinline__ void cp_wait() {
    asm volatile("cp.async.wait_group %0;\n" :: "n"(N));
}
#define LDSM_X4(r0, r1, r2, r3, addr) \
    asm volatile("ldmatrix.sync.aligned.m8n8.x4.shared.b16 {%0,%1,%2,%3}, [%4];" \
                 : "=r"(r0), "=r"(r1), "=r"(r2), "=r"(r3) : "r"(addr))
#define LDSM_X4_T(r0, r1, r2, r3, addr) \
    asm volatile("ldmatrix.sync.aligned.m8n8.x4.trans.shared.b16 {%0,%1,%2,%3}, [%4];" \
                 : "=r"(r0), "=r"(r1), "=r"(r2), "=r"(r3) : "r"(addr))
#define LDSM_X2(r0, r1, addr) \
    asm volatile("ldmatrix.sync.aligned.m8n8.x2.shared.b16 {%0,%1}, [%2];" \
                 : "=r"(r0), "=r"(r1) : "r"(addr))

// ---------------- fp16 3-stage GEMM ----------------
// acc = sum_k A[m][k]*B[k][n]  (A fp16 [M][K] lda, B fp16 [K][N] ldb, K=256)
// OMODE 0: Y fp32.  OMODE 1: fp16 transposed per 64-row head.
// OMODE 3: DUAL (z even: K transposed; z odd: V direct fp16).
template <int BM, int TMt, int OMODE>
__global__ __launch_bounds__(256, 2) void hgemm(
    const __half* __restrict__ A, const __half* __restrict__ A2,
    const __half* __restrict__ B,
    float* __restrict__ Y, __half* __restrict__ Yh, __half* __restrict__ Yh2,
    int lda, int ldb, int ldy,
    long aB, long bB, long yB, float alpha, float beta,
    const float* __restrict__ rs,
    const float* __restrict__ rb, const float* __restrict__ rb2)
{
    extern __shared__ __half smH[];
    __half* sA = smH;                   // [3][BM][40]
    __half* sB = smH + 3 * BM * 40;     // [3][32][136]

    int sel = 0;
    long zb;
    if (OMODE == 3) {
        sel = blockIdx.z & 1;
        zb  = blockIdx.z >> 1;
        if (sel) { A = A2; rb = rb2; }
    } else {
        zb = blockIdx.z;
    }
    A += zb * aB;
    B += zb * bB;

    const int tid  = threadIdx.x;
    const int lane = tid & 31;
    const int wid  = tid >> 5;
    const int wm   = wid >> 2;
    const int wn   = wid & 3;
    const int g    = lane >> 2;
    const int tig  = lane & 3;
    const int m0   = blockIdx.y * BM;
    const int n0   = blockIdx.x * 128;

    const uint32_t a_off = ((lane & 15) * 40 + (lane >> 4) * 8) * 2;
    const uint32_t b_off = ((lane & 15) * 136 + (lane >> 4) * 8) * 2;

    float4 acc[TMt][4];
#pragma unroll
    for (int i = 0; i < TMt; i++)
#pragma unroll
        for (int j = 0; j < 4; j++) acc[i][j] = make_float4(0.f, 0.f, 0.f, 0.f);

    auto prefetch = [&](int t, int buf) {
        __half* dA = sA + buf * BM * 40;
        __half* dB = sB + buf * 32 * 136;
#pragma unroll
        for (int i = tid; i < BM * 4; i += 256) {
            int r = i >> 2, c = (i & 3) * 8;
            cpa16(stou(dA + r * 40 + c), A + (long)(m0 + r) * lda + t * 32 + c);
        }
#pragma unroll
        for (int i = tid; i < 512; i += 256) {
            int r = i >> 4, c = (i & 15) * 8;
            cpa16(stou(dB + r * 136 + c), B + (long)(t * 32 + r) * ldb + n0 + c);
        }
    };

    prefetch(0, 0); cp_commit();
    prefetch(1, 1); cp_commit();

    for (int t = 0; t < 8; t++) {
        if (t < 7) cp_wait<1>(); else cp_wait<0>();
        __syncthreads();
        if (t + 2 < 8) { prefetch(t + 2, (t + 2) % 3); cp_commit(); }

        const uint32_t aBase = stou(sA) + (uint32_t)((t % 3) * BM * 40 * 2);
        const uint32_t bBase = stou(sB) + (uint32_t)((t % 3) * 32 * 136 * 2);

#pragma unroll
        for (int s = 0; s < 2; s++) {
            uint32_t a[TMt][4];
#pragma unroll
            for (int mt = 0; mt < TMt; mt++)
                LDSM_X4(a[mt][0], a[mt][1], a[mt][2], a[mt][3],
                        aBase + (uint32_t)(((wm * TMt * 16 + mt * 16) * 40 + s * 16) * 2) + a_off);
            uint32_t b[2][4];
#pragma unroll
            for (int j = 0; j < 2; j++)
                LDSM_X4_T(b[j][0], b[j][1], b[j][2], b[j][3],
                          bBase + (uint32_t)((s * 16 * 136 + wn * 32 + j * 16) * 2) + b_off);
#pragma unroll
            for (int mt = 0; mt < TMt; mt++)
#pragma unroll
                for (int nt = 0; nt < 4; nt++)
                    mma_f16(acc[mt][nt], a[mt][0], a[mt][1], a[mt][2], a[mt][3],
                            b[nt >> 1][(nt & 1) * 2], b[nt >> 1][(nt & 1) * 2 + 1]);
        }
    }

    const bool kpath = (OMODE == 1) || (OMODE == 3 && sel == 0);
    if (kpath) {
        __syncthreads();
        __half* sT = smH;
        const int st = BM + 2;
#pragma unroll
        for (int mt = 0; mt < TMt; mt++) {
            int rl = wm * (TMt * 16) + mt * 16 + g;
            int r = m0 + rl;
            float t0 = beta * (rb ? rb[r] : 0.0f);
            float t1 = beta * (rb ? rb[r + 8] : 0.0f);
#pragma unroll
            for (int nt = 0; nt < 4; nt++) {
                int c = wn * 32 + nt * 8 + 2 * tig;
                sT[c * st + rl]           = __float2half_rn(acc[mt][nt].x * alpha + t0);
                sT[(c + 1) * st + rl]     = __float2half_rn(acc[mt][nt].y * alpha + t0);
                sT[c * st + rl + 8]       = __float2half_rn(acc[mt][nt].z * alpha + t1);
                sT[(c + 1) * st + rl + 8] = __float2half_rn(acc[mt][nt].w * alpha + t1);
            }
        }
        __syncthreads();
        uint32_t* Y32 = reinterpret_cast<uint32_t*>(Yh);
        for (int i = tid; i < 128 * (BM / 2); i += 256) {
            int lc = i / (BM / 2);
            int rp = (i % (BM / 2)) * 2;
            uint32_t v = *reinterpret_cast<uint32_t*>(&sT[lc * st + rp]);
            int r = m0 + rp;
            int h = r >> 6, e = r & 63;
            Y32[((zb * HH + h) * (long)ldy + n0 + lc) * 32 + (e >> 1)] = v;
        }
    } else {
#pragma unroll
        for (int mt = 0; mt < TMt; mt++) {
            int r = m0 + wm * (TMt * 16) + mt * 16 + g;
            float s0 = alpha * (rs ? rs[r] : 1.0f),     t0 = beta * (rb ? rb[r] : 0.0f);
            float s1 = alpha * (rs ? rs[r + 8] : 1.0f), t1 = beta * (rb ? rb[r + 8] : 0.0f);
#pragma unroll
            for (int nt = 0; nt < 4; nt++) {
                int c = n0 + wn * 32 + nt * 8 + 2 * tig;
                float y00 = acc[mt][nt].x * s0 + t0, y01 = acc[mt][nt].y * s0 + t0;
                float y10 = acc[mt][nt].z * s1 + t1, y11 = acc[mt][nt].w * s1 + t1;
                if (OMODE == 3) {
                    uint32_t* Y32 = reinterpret_cast<uint32_t*>(Yh2);
                    Y32[((zb * CCH + r) * (long)ldy + c) >> 1]     = h2pack(y00, y01);
                    Y32[((zb * CCH + r + 8) * (long)ldy + c) >> 1] = h2pack(y10, y11);
                } else {
                    float* Yb = Y + zb * yB;
                    *reinterpret_cast<float2*>(Yb + (long)r * ldy + c) = make_float2(y00, y01);
                    *reinterpret_cast<float2*>(Yb + (long)(r + 8) * ldy + c) = make_float2(y10, y11);
                }
            }
        }
    }
}

#define HGEMM128_SMEM (3 * (128 * 40 + 32 * 136) * 2)
#define HGEMM64_SMEM  (3 * (64 * 40 + 32 * 136) * 2)

// ---------------- fused flash attention: max-free softmax, 2 CTAs/SM ----------------
// Q: [l][64e] (log2 domain), K: [m][64e], V: [64e][m] fp16.  4 warps; warp w owns q rows w*16..+16.
// S range-analysis-bounded: P = exp2(S) directly in fp16; rowsum via ones-row mma.
#define SQH 0
#define SKH (64 * 72)
#define SVH (SKH + 2 * 128 * 72)
#define FLASH_SMEM_BYTES ((SVH + 2 * 72 * 136) * 2)

__global__ __launch_bounds__(128, 2) void flash_kernel(
    const __half* __restrict__ Qh, const __half* __restrict__ Kh,
    const __half* __restrict__ Vh, __half* __restrict__ O)
{
    extern __shared__ __half smh[];
    __half* sQ = smh + SQH;
    __half* sK = smh + SKH;
    __half* sV = smh + SVH;

    const int tid  = threadIdx.x;
    const int lane = tid & 31;
    const int w    = tid >> 5;
    const int g    = lane >> 2;
    const int tig  = lane & 3;

    const int l0 = blockIdx.x * 64;
    const int nh = blockIdx.y;
    const int n  = nh >> 2, h = nh & 3;
    const __half* qb = Qh + (((long)(n * HH + h)) * LF + l0) * EE;
    const __half* kb = Kh + ((long)(n * HH + h)) * L2 * EE;
    const __half* vb = Vh + ((long)(n * HH + h)) * EE * L2;
    __half*       ob = O + ((long)n * CCH + h * 64) * LF + l0;

    const int row_lo = w * 16 + g;
    const int row_hi = row_lo + 8;

    const int qrow = lane & 7;
    const int sel  = lane >> 3;
    const uint32_t sQb = stou(sQ), sKb0 = stou(sK), sVb0 = stou(sV);
    const uint32_t qa_off = ((w * 16 + (lane & 15)) * 72 + (lane >> 4) * 8) * 2;
    const uint32_t kb_off = (((sel >> 1) * 8 + qrow) * 72 + (sel & 1) * 8) * 2;
    const uint32_t vb_off = (((sel >> 1) * 8 + qrow) * 136 + (sel & 1) * 8) * 2;
    const uint32_t v2_off = ((64 + qrow) * 136 + ((lane >> 3) & 1) * 8) * 2;

    // prologue: Q (group 0); K0+V0 (group 1)
#pragma unroll
    for (int i = 0; i < 4; i++) {
        int idx = tid + i * 128;
        int r = idx >> 3, c8 = idx & 7;
        cpa16(stou(sQ + r * 72 + c8 * 8), qb + (long)r * EE + c8 * 8);
    }
    cp_commit();
#pragma unroll
    for (int i = 0; i < 8; i++) {
        int idx = tid + i * 128;
        int r = idx >> 3, c8 = idx & 7;
        cpa16(stou(sK + r * 72 + c8 * 8), kb + (long)r * EE + c8 * 8);
    }
#pragma unroll
    for (int i = 0; i < 8; i++) {
        int idx = tid + i * 128;
        int r = idx >> 4, c16 = idx & 15;
        cpa16(stou(sV + r * 136 + c16 * 8), vb + (long)r * L2 + c16 * 8);
    }
    cp_commit();

    // ones/zeros rows 64-71 of both V buffers
    {
        uint32_t* sV32w = reinterpret_cast<uint32_t*>(sV);
        for (int i = tid; i < 2 * 8 * 68; i += 128) {
            int buf = i / (8 * 68);
            int rem = i % (8 * 68);
            int r = rem / 68, c = rem % 68;
            sV32w[buf * (72 * 68) + (64 + r) * 68 + c] = (r == 0) ? 0x3C003C00u : 0u;
        }
    }

    float4 accO[9];
#pragma unroll
    for (int nt = 0; nt < 9; nt++) accO[nt] = make_float4(0.f, 0.f, 0.f, 0.f);

    cp_wait<0>();
    __syncthreads();

    uint32_t qa[4][4];
#pragma unroll
    for (int kk = 0; kk < 4; kk++)
        LDSM_X4(qa[kk][0], qa[kk][1], qa[kk][2], qa[kk][3], sQb + qa_off + kk * 32);

#pragma unroll 1
    for (int t = 0; t < 8; t++) {
        if (t > 0) {
            cp_wait<0>();
            __syncthreads();
        }
        if (t < 7) {
            __half* dK = sK + ((t + 1) & 1) * (128 * 72);
            const __half* ksrc = kb + (long)(t + 1) * 128 * EE;
#pragma unroll
            for (int i = 0; i < 8; i++) {
                int idx = tid + i * 128;
                int r = idx >> 3, c8 = idx & 7;
                cpa16(stou(dK + r * 72 + c8 * 8), ksrc + (long)r * EE + c8 * 8);
            }
            __half* dV = sV + ((t + 1) & 1) * (72 * 136);
#pragma unroll
            for (int i = 0; i < 8; i++) {
                int idx = tid + i * 128;
                int r = idx >> 4, c16 = idx & 15;
                cpa16(stou(dV + r * 136 + c16 * 8), vb + (long)r * L2 + (t + 1) * 128 + c16 * 8);
            }
            cp_commit();
        }

        const uint32_t kbase = sKb0 + (uint32_t)((t & 1) * (128 * 72 * 2));
        const uint32_t vbase = sVb0 + (uint32_t)((t & 1) * (72 * 136 * 2));

        // ---- S = Q K^T ----
        float4 accS[16];
#pragma unroll
        for (int nt = 0; nt < 16; nt++) accS[nt] = make_float4(0.f, 0.f, 0.f, 0.f);

#pragma unroll
        for (int kk = 0; kk < 4; kk++) {
#pragma unroll
            for (int jp = 0; jp < 8; jp++) {
                uint32_t b0, b1, b2, b3;
                LDSM_X4(b0, b1, b2, b3, kbase + jp * (16 * 72 * 2) + kk * 32 + kb_off);
                mma_f16(accS[2 * jp],     qa[kk][0], qa[kk][1], qa[kk][2], qa[kk][3], b0, b1);
                mma_f16(accS[2 * jp + 1], qa[kk][0], qa[kk][1], qa[kk][2], qa[kk][3], b2, b3);
            }
        }

        // ---- P = exp2(S) directly (max-free; range bounded by construction) ----
        uint32_t pLo[16], pHi[16];
#pragma unroll
        for (int nt = 0; nt < 16; nt++) {
            pLo[nt] = ex2h2(h2pack(accS[nt].x, accS[nt].y));
            pHi[nt] = ex2h2(h2pack(accS[nt].z, accS[nt].w));
        }

        // ---- O += P V^T (and row-sum via ones tile) ----
#pragma unroll
        for (int kk = 0; kk < 8; kk++) {
            uint32_t a0 = pLo[2 * kk], a1 = pHi[2 * kk];
            uint32_t a2 = pLo[2 * kk + 1], a3 = pHi[2 * kk + 1];
#pragma unroll
            for (int jp = 0; jp < 4; jp++) {
                uint32_t b0, b1, b2, b3;
                LDSM_X4(b0, b1, b2, b3, vbase + jp * (16 * 136 * 2) + kk * 32 + vb_off);
                mma_f16(accO[2 * jp],     a0, a1, a2, a3, b0, b1);
                mma_f16(accO[2 * jp + 1], a0, a1, a2, a3, b2, b3);
            }
            uint32_t c0, c1;
            LDSM_X2(c0, c1, vbase + kk * 32 + v2_off);
            mma_f16(accO[8], a0, a1, a2, a3, c0, c1);
        }
    }

    // ---- epilogue: O[e][l] = accO / rowsum ----
    float s_lo = __shfl_sync(0xffffffffu, accO[8].x, lane & ~3);
    float s_hi = __shfl_sync(0xffffffffu, accO[8].z, lane & ~3);
    float i_lo = 1.0f / s_lo;
    float i_hi = 1.0f / s_hi;
#pragma unroll
    for (int nt = 0; nt < 8; nt++) {
        int e = nt * 8 + 2 * tig;
        ob[(long)e * LF + row_lo]       = __float2half_rn(accO[nt].x * i_lo);
        ob[(long)(e + 1) * LF + row_lo] = __float2half_rn(accO[nt].y * i_lo);
        ob[(long)e * LF + row_hi]       = __float2half_rn(accO[nt].z * i_hi);
        ob[(long)(e + 1) * LF + row_hi] = __float2half_rn(accO[nt].w * i_hi);
    }
}

// ---------------- launch ----------------
extern "C" void kernel_launch(void* const* d_in, const int* in_sizes, int n_in,
                              void* d_out, int out_size) {
    const float* x  = (const float*)d_in[0];
    const float* Wq = (const float*)d_in[1];  const float* bq = (const float*)d_in[2];
    const float* Wk = (const float*)d_in[3];  const float* bk = (const float*)d_in[4];
    const float* Wv = (const float*)d_in[5];  const float* bv = (const float*)d_in[6];
    const float* Wo = (const float*)d_in[7];  const float* bo = (const float*)d_in[8];
    const float* Wa = (const float*)d_in[9];
    const float* g1 = (const float*)d_in[10]; const float* b1 = (const float*)d_in[11];
    const float* m1 = (const float*)d_in[12]; const float* v1 = (const float*)d_in[13];
    const float* g2 = (const float*)d_in[14]; const float* b2 = (const float*)d_in[15];
    const float* m2 = (const float*)d_in[16]; const float* v2 = (const float*)d_in[17];
    float* out = (float*)d_out;
    (void)in_sizes; (void)n_in; (void)out_size;

    __half *pXh, *pXaggh, *pQh, *pKh, *pVh, *pOh;
    __half *pWqh, *pWoh, *pWke, *pWve;
    float *pBke, *pBve;
    cudaGetSymbolAddress((void**)&pXh,    d_xh);
    cudaGetSymbolAddress((void**)&pXaggh, d_xaggh);
    cudaGetSymbolAddress((void**)&pQh,    d_qh);
    cudaGetSymbolAddress((void**)&pKh,    d_kh);
    cudaGetSymbolAddress((void**)&pVh,    d_vh);
    cudaGetSymbolAddress((void**)&pOh,    d_oh);
    cudaGetSymbolAddress((void**)&pWqh,   d_wqh);
    cudaGetSymbolAddress((void**)&pWoh,   d_woh);
    cudaGetSymbolAddress((void**)&pWke,   d_wke);
    cudaGetSymbolAddress((void**)&pWve,   d_wve);
    cudaGetSymbolAddress((void**)&pBke,   d_bke);
    cudaGetSymbolAddress((void**)&pBve,   d_bve);

    cudaFuncSetAttribute(flash_kernel, cudaFuncAttributeMaxDynamicSharedMemorySize,
                         FLASH_SMEM_BYTES);
    cudaFuncSetAttribute(hgemm<128, 4, 0>, cudaFuncAttributeMaxDynamicSharedMemorySize,
                         HGEMM128_SMEM);
    cudaFuncSetAttribute(hgemm<128, 4, 1>, cudaFuncAttributeMaxDynamicSharedMemorySize,
                         HGEMM128_SMEM);
    cudaFuncSetAttribute(hgemm<64, 2, 3>, cudaFuncAttributeMaxDynamicSharedMemorySize,
                         HGEMM64_SMEM);

    const float QSCALE = 0.125f * 1.44269504089f;  // fold 1/sqrt(E) and log2e into Q

    // 1) prep (x->fp16 + pool, Wq/Wo->fp16) and BN-fold of K/V weights
    prep_kernel<<<NB * CCH + 64, 256>>>(x, Wq, Wo);
    wfold_kernel<<<dim3(4, 4, 2), 256>>>(Wk, Wv, Wa, bk, bv,
                                         g1, b1, m1, v1, g2, b2, m2, v2);

    // 2) Q = fp16[l][e] of log2e*0.125*(Wq x + bq)
    hgemm<128, 4, 1><<<dim3(LF / 128, CCH / 128, NB), 256, HGEMM128_SMEM>>>(
        pWqh, nullptr, pXh, nullptr, pQh, nullptr, CCH, LF, LF,
        0, (long)CCH * LF, 0, QSCALE, QSCALE, nullptr, bq, nullptr);

    // 3) K (transposed) and V (direct) straight from xagg via folded weights
    hgemm<64, 2, 3><<<dim3(L2 / 128, CCH / 64, NB * 2), 256, HGEMM64_SMEM>>>(
        pWke, pWve, pXaggh, nullptr, pKh, pVh, CCH, L2, L2,
        0, (long)CCH * L2, 0, 1.0f, 1.0f, nullptr, pBke, pBve);

    // 4) fused attention (max-free softmax)
    flash_kernel<<<dim3(LF / 64, NB * HH), 128, FLASH_SMEM_BYTES>>>(pQh, pKh, pVh, pOh);

    // 5) out = Wo @ o + bo
    hgemm<128, 4, 0><<<dim3(LF / 128, CCH / 128, NB), 256, HGEMM128_SMEM>>>(
        pWoh, nullptr, pOh, out, nullptr, nullptr, CCH, LF, LF,
        0, (long)CCH * LF, (long)CCH * LF, 1.0f, 1.0f, nullptr, bo, nullptr);
}

// round 15
// speedup vs baseline: 1.4427x; 1.4427x over previous
#include <cuda_runtime.h>
#include <cuda_fp16.h>
#include <cstdint>

// Problem constants
#define NB  4
#define CCH 256
#define LF  4096
#define L2  1024
#define HH  4
#define EE  64

// ---------------- device scratch (static; no cudaMalloc) ----------------
__device__ __half d_xh   [NB * CCH * LF];
__device__ __half d_xaggh[NB * CCH * L2];
__device__ __half d_xah  [NB * CCH * L2];
__device__ __half d_qh   [NB * HH * LF * EE];  // [n][h][l][e], log2e*0.125*(Wq x + bq)
__device__ __half d_kh   [NB * HH * L2 * EE];  // [n][h][m][e]
__device__ __half d_vh   [NB * HH * EE * L2];  // [n][h][e][m]
__device__ __half d_oh   [NB * CCH * LF];
__device__ __half d_wqh[CCH * CCH], d_wkh[CCH * CCH], d_wvh[CCH * CCH];
__device__ __half d_woh[CCH * CCH], d_wah[CCH * CCH];
__device__ float  d_bns[CCH];
__device__ float  d_bnt[CCH];

// ---------------- fused prep: x->fp16 + pooling, weights->fp16, BN fold ----------------
// grid 1185 x 256: blocks [0,1024) process one (n,c) row each; [1024,1184) weights; 1184 BN.
__global__ void prep_kernel(const float* __restrict__ x,
                            const float* __restrict__ wq, const float* __restrict__ wk,
                            const float* __restrict__ wv, const float* __restrict__ wo,
                            const float* __restrict__ wa,
                            const float* __restrict__ g1, const float* __restrict__ b1,
                            const float* __restrict__ m1, const float* __restrict__ v1,
                            const float* __restrict__ g2, const float* __restrict__ b2,
                            const float* __restrict__ m2, const float* __restrict__ v2) {
    int b = blockIdx.x;
    int tid = threadIdx.x;
    if (b < NB * CCH) {
        const float4* xr = reinterpret_cast<const float4*>(x + (long)b * LF);
        __half2* xo = reinterpret_cast<__half2*>(d_xh) + (long)b * (LF / 2);
        __half*  ao = d_xaggh + (long)b * L2;
#pragma unroll
        for (int k = 0; k < 4; k++) {
            int j = tid + k * 256;              // float4 index = pool group index
            float4 t = xr[j];
            xo[2 * j]     = __floats2half2_rn(t.x, t.y);
            xo[2 * j + 1] = __floats2half2_rn(t.z, t.w);
            float mx = fmaxf(fmaxf(t.x, t.y), fmaxf(t.z, t.w));
            ao[j] = __float2half_rn(0.25f * (t.x + t.y + t.z + t.w) + mx);
        }
    } else if (b < NB * CCH + 160) {
        const float* src[5] = {wq, wk, wv, wo, wa};
        __half* dst[5] = {d_wqh, d_wkh, d_wvh, d_woh, d_wah};
#pragma unroll
        for (int k = 0; k < 2; k++) {
            int idx = (b - NB * CCH) * 512 + k * 256 + tid;   // float4 idx in [0, 81920)
            int m = idx >> 14;                                 // /16384
            int j = idx & 16383;
            float4 t = reinterpret_cast<const float4*>(src[m])[j];
            __half2* o = reinterpret_cast<__half2*>(dst[m]);
            o[2 * j]     = __floats2half2_rn(t.x, t.y);
            o[2 * j + 1] = __floats2half2_rn(t.z, t.w);
        }
    } else {
        int c = tid;
        float i1 = g1[c] * rsqrtf(v1[c] + 1e-5f);
        float c1 = b1[c] - m1[c] * i1;
        float i2 = g2[c] * rsqrtf(v2[c] + 1e-5f);
        float c2 = b2[c] - m2[c] * i2;
        d_bns[c] = i1 * i2;
        d_bnt[c] = c1 * i2 + c2;
    }
}

// ---------------- helpers ----------------
__device__ __forceinline__ void mma_f16(float4& c, uint32_t a0, uint32_t a1, uint32_t a2,
                                        uint32_t a3, uint32_t b0, uint32_t b1) {
    asm volatile(
        "mma.sync.aligned.m16n8k16.row.col.f32.f16.f16.f32 "
        "{%0,%1,%2,%3}, {%4,%5,%6,%7}, {%8,%9}, {%0,%1,%2,%3};\n"
        : "+f"(c.x), "+f"(c.y), "+f"(c.z), "+f"(c.w)
        : "r"(a0), "r"(a1), "r"(a2), "r"(a3), "r"(b0), "r"(b1));
}
__device__ __forceinline__ uint32_t h2pack(float a, float b) {
    __half2 h = __floats2half2_rn(a, b);
    return *reinterpret_cast<uint32_t*>(&h);
}
__device__ __forceinline__ uint32_t ex2h2(uint32_t in) {
    uint32_t r;
    asm("ex2.approx.f16x2 %0, %1;" : "=r"(r) : "r"(in));
    return r;
}
__device__ __forceinline__ uint32_t stou(const void* p) {
    return (uint32_t)__cvta_generic_to_shared(p);
}
__device__ __forceinline__ void cpa16(uint32_t dst, const void* src) {
    asm volatile("cp.async.cg.shared.global [%0], [%1], 16;\n" :: "r"(dst), "l"(src));
}
__device__ __forceinline__ void cp_commit() { asm volatile("cp.async.commit_group;\n"); }
template <int N> __device__ __forceinline__ void cp_wait() {
    asm volatile("cp.async.wait_group %0;\n" :: "n"(N));
}
#define LDSM_X4(r0, r1, r2, r3, addr) \
    asm volatile("ldmatrix.sync.aligned.m8n8.x4.shared.b16 {%0,%1,%2,%3}, [%4];" \
                 : "=r"(r0), "=r"(r1), "=r"(r2), "=r"(r3) : "r"(addr))
#define LDSM_X4_T(r0, r1, r2, r3, addr) \
    asm volatile("ldmatrix.sync.aligned.m8n8.x4.trans.shared.b16 {%0,%1,%2,%3}, [%4];" \
                 : "=r"(r0), "=r"(r1), "=r"(r2), "=r"(r3) : "r"(addr))
#define LDSM_X2(r0, r1, addr) \
    asm volatile("ldmatrix.sync.aligned.m8n8.x2.shared.b16 {%0,%1}, [%2];" \
                 : "=r"(r0), "=r"(r1) : "r"(addr))

// ---------------- fp16 3-stage GEMM ----------------
// acc = sum_k A[m][k]*B[k][n]  (A fp16 [M][K] lda, B fp16 [K][N] ldb, K=256)
// OMODE 0: Y fp32.  OMODE 1: fp16 transposed per 64-row head.
// OMODE 2: fp16 direct.  OMODE 3: DUAL (z even: K transposed; z odd: V direct).
template <int BM, int TMt, int OMODE>
__global__ __launch_bounds__(256, 2) void hgemm(
    const __half* __restrict__ A, const __half* __restrict__ A2,
    const __half* __restrict__ B,
    float* __restrict__ Y, __half* __restrict__ Yh, __half* __restrict__ Yh2,
    int lda, int ldb, int ldy,
    long aB, long bB, long yB, float alpha, float beta,
    const float* __restrict__ rs,
    const float* __restrict__ rb, const float* __restrict__ rb2)
{
    extern __shared__ __half smH[];
    __half* sA = smH;                   // [3][BM][40]
    __half* sB = smH + 3 * BM * 40;     // [3][32][136]

    int sel = 0;
    long zb;
    if (OMODE == 3) {
        sel = blockIdx.z & 1;
        zb  = blockIdx.z >> 1;
        if (sel) { A = A2; rb = rb2; }
    } else {
        zb = blockIdx.z;
    }
    A += zb * aB;
    B += zb * bB;

    const int tid  = threadIdx.x;
    const int lane = tid & 31;
    const int wid  = tid >> 5;
    const int wm   = wid >> 2;
    const int wn   = wid & 3;
    const int g    = lane >> 2;
    const int tig  = lane & 3;
    const int m0   = blockIdx.y * BM;
    const int n0   = blockIdx.x * 128;

    const uint32_t a_off = ((lane & 15) * 40 + (lane >> 4) * 8) * 2;
    const uint32_t b_off = ((lane & 15) * 136 + (lane >> 4) * 8) * 2;

    float4 acc[TMt][4];
#pragma unroll
    for (int i = 0; i < TMt; i++)
#pragma unroll
        for (int j = 0; j < 4; j++) acc[i][j] = make_float4(0.f, 0.f, 0.f, 0.f);

    auto prefetch = [&](int t, int buf) {
        __half* dA = sA + buf * BM * 40;
        __half* dB = sB + buf * 32 * 136;
#pragma unroll
        for (int i = tid; i < BM * 4; i += 256) {
            int r = i >> 2, c = (i & 3) * 8;
            cpa16(stou(dA + r * 40 + c), A + (long)(m0 + r) * lda + t * 32 + c);
        }
#pragma unroll
        for (int i = tid; i < 512; i += 256) {
            int r = i >> 4, c = (i & 15) * 8;
            cpa16(stou(dB + r * 136 + c), B + (long)(t * 32 + r) * ldb + n0 + c);
        }
    };

    prefetch(0, 0); cp_commit();
    prefetch(1, 1); cp_commit();

    for (int t = 0; t < 8; t++) {
        if (t < 7) cp_wait<1>(); else cp_wait<0>();
        __syncthreads();
        if (t + 2 < 8) { prefetch(t + 2, (t + 2) % 3); cp_commit(); }

        const uint32_t aBase = stou(sA) + (uint32_t)((t % 3) * BM * 40 * 2);
        const uint32_t bBase = stou(sB) + (uint32_t)((t % 3) * 32 * 136 * 2);

#pragma unroll
        for (int s = 0; s < 2; s++) {
            uint32_t a[TMt][4];
#pragma unroll
            for (int mt = 0; mt < TMt; mt++)
                LDSM_X4(a[mt][0], a[mt][1], a[mt][2], a[mt][3],
                        aBase + (uint32_t)(((wm * TMt * 16 + mt * 16) * 40 + s * 16) * 2) + a_off);
            uint32_t b[2][4];
#pragma unroll
            for (int j = 0; j < 2; j++)
                LDSM_X4_T(b[j][0], b[j][1], b[j][2], b[j][3],
                          bBase + (uint32_t)((s * 16 * 136 + wn * 32 + j * 16) * 2) + b_off);
#pragma unroll
            for (int mt = 0; mt < TMt; mt++)
#pragma unroll
                for (int nt = 0; nt < 4; nt++)
                    mma_f16(acc[mt][nt], a[mt][0], a[mt][1], a[mt][2], a[mt][3],
                            b[nt >> 1][(nt & 1) * 2], b[nt >> 1][(nt & 1) * 2 + 1]);
        }
    }

    const bool kpath = (OMODE == 1) || (OMODE == 3 && sel == 0);
    if (kpath) {
        __syncthreads();
        __half* sT = smH;
        const int st = BM + 2;
#pragma unroll
        for (int mt = 0; mt < TMt; mt++) {
            int rl = wm * (TMt * 16) + mt * 16 + g;
            int r = m0 + rl;
            float t0 = beta * (rb ? rb[r] : 0.0f);
            float t1 = beta * (rb ? rb[r + 8] : 0.0f);
#pragma unroll
            for (int nt = 0; nt < 4; nt++) {
                int c = wn * 32 + nt * 8 + 2 * tig;
                sT[c * st + rl]           = __float2half_rn(acc[mt][nt].x * alpha + t0);
                sT[(c + 1) * st + rl]     = __float2half_rn(acc[mt][nt].y * alpha + t0);
                sT[c * st + rl + 8]       = __float2half_rn(acc[mt][nt].z * alpha + t1);
                sT[(c + 1) * st + rl + 8] = __float2half_rn(acc[mt][nt].w * alpha + t1);
            }
        }
        __syncthreads();
        uint32_t* Y32 = reinterpret_cast<uint32_t*>(Yh);
        for (int i = tid; i < 128 * (BM / 2); i += 256) {
            int lc = i / (BM / 2);
            int rp = (i % (BM / 2)) * 2;
            uint32_t v = *reinterpret_cast<uint32_t*>(&sT[lc * st + rp]);
            int r = m0 + rp;
            int h = r >> 6, e = r & 63;
            Y32[((zb * HH + h) * (long)ldy + n0 + lc) * 32 + (e >> 1)] = v;
        }
    } else {
#pragma unroll
        for (int mt = 0; mt < TMt; mt++) {
            int r = m0 + wm * (TMt * 16) + mt * 16 + g;
            float s0 = alpha * (rs ? rs[r] : 1.0f),     t0 = beta * (rb ? rb[r] : 0.0f);
            float s1 = alpha * (rs ? rs[r + 8] : 1.0f), t1 = beta * (rb ? rb[r + 8] : 0.0f);
#pragma unroll
            for (int nt = 0; nt < 4; nt++) {
                int c = n0 + wn * 32 + nt * 8 + 2 * tig;
                float y00 = acc[mt][nt].x * s0 + t0, y01 = acc[mt][nt].y * s0 + t0;
                float y10 = acc[mt][nt].z * s1 + t1, y11 = acc[mt][nt].w * s1 + t1;
                if (OMODE == 2 || OMODE == 3) {
                    __half* Yd = (OMODE == 3) ? Yh2 : Yh;
                    uint32_t* Y32 = reinterpret_cast<uint32_t*>(Yd);
                    Y32[((zb * CCH + r) * (long)ldy + c) >> 1]     = h2pack(y00, y01);
                    Y32[((zb * CCH + r + 8) * (long)ldy + c) >> 1] = h2pack(y10, y11);
                } else {
                    float* Yb = Y + zb * yB;
                    *reinterpret_cast<float2*>(Yb + (long)r * ldy + c) = make_float2(y00, y01);
                    *reinterpret_cast<float2*>(Yb + (long)(r + 8) * ldy + c) = make_float2(y10, y11);
                }
            }
        }
    }
}

#define HGEMM128_SMEM (3 * (128 * 40 + 32 * 136) * 2)
#define HGEMM64_SMEM  (3 * (64 * 40 + 32 * 136) * 2)

// ---------------- fused flash attention: 128 threads, 2 CTAs/SM, max-free softmax ----------------
// Q: [l][64e] (log2 domain), K: [m][64e], V: [64e][m] fp16.  4 warps; warp w owns q rows w*16..+16.
// S is range-bounded (|S| << 15 in log2 domain), so P = exp2(S) directly; rowsum via ones-row mma.
#define SQH 0
#define SKH (64 * 72)
#define SVH (SKH + 2 * 128 * 72)
#define FLASH_SMEM_BYTES ((SVH + 2 * 72 * 136) * 2)   // 85,248 B

__global__ __launch_bounds__(128, 2) void flash_kernel(
    const __half* __restrict__ Qh, const __half* __restrict__ Kh,
    const __half* __restrict__ Vh, __half* __restrict__ O)
{
    extern __shared__ __half smh[];
    __half* sQ = smh + SQH;
    __half* sK = smh + SKH;
    __half* sV = smh + SVH;

    const int tid  = threadIdx.x;
    const int lane = tid & 31;
    const int w    = tid >> 5;      // 0..3
    const int g    = lane >> 2;
    const int tig  = lane & 3;

    const int l0 = blockIdx.x * 64;
    const int nh = blockIdx.y;
    const int n  = nh >> 2, h = nh & 3;
    const __half* qb = Qh + (((long)(n * HH + h)) * LF + l0) * EE;
    const __half* kb = Kh + ((long)(n * HH + h)) * L2 * EE;
    const __half* vb = Vh + ((long)(n * HH + h)) * EE * L2;
    __half*       ob = O + ((long)n * CCH + h * 64) * LF + l0;

    const int row_lo = w * 16 + g;
    const int row_hi = row_lo + 8;

    const int qrow = lane & 7;
    const int sel  = lane >> 3;
    const uint32_t sQb = stou(sQ), sKb0 = stou(sK), sVb0 = stou(sV);
    const uint32_t qa_off = ((w * 16 + (lane & 15)) * 72 + (lane >> 4) * 8) * 2;
    const uint32_t kb_off = (((sel >> 1) * 8 + qrow) * 72 + (sel & 1) * 8) * 2;
    const uint32_t vb_off = (((sel >> 1) * 8 + qrow) * 136 + (sel & 1) * 8) * 2;
    const uint32_t v2_off = ((64 + qrow) * 136 + ((lane >> 3) & 1) * 8) * 2;

    // prologue: Q (group 0); K0+V0 (group 1)
#pragma unroll
    for (int i = 0; i < 4; i++) {
        int idx = tid + i * 128;
        int r = idx >> 3, c8 = idx & 7;
        cpa16(stou(sQ + r * 72 + c8 * 8), qb + (long)r * EE + c8 * 8);
    }
    cp_commit();
#pragma unroll
    for (int i = 0; i < 8; i++) {
        int idx = tid + i * 128;
        int r = idx >> 3, c8 = idx & 7;
        cpa16(stou(sK + r * 72 + c8 * 8), kb + (long)r * EE + c8 * 8);
    }
#pragma unroll
    for (int i = 0; i < 8; i++) {
        int idx = tid + i * 128;
        int r = idx >> 4, c16 = idx & 15;
        cpa16(stou(sV + r * 136 + c16 * 8), vb + (long)r * L2 + c16 * 8);
    }
    cp_commit();

    // ones/zeros rows 64-71 of both V buffers
    {
        uint32_t* sV32w = reinterpret_cast<uint32_t*>(sV);
        for (int i = tid; i < 2 * 8 * 68; i += 128) {
            int buf = i / (8 * 68);
            int rem = i % (8 * 68);
            int r = rem / 68, c = rem % 68;
            sV32w[buf * (72 * 68) + (64 + r) * 68 + c] = (r == 0) ? 0x3C003C00u : 0u;
        }
    }

    float4 accO[9];
#pragma unroll
    for (int nt = 0; nt < 9; nt++) accO[nt] = make_float4(0.f, 0.f, 0.f, 0.f);

    cp_wait<0>();
    __syncthreads();

    uint32_t qa[4][4];
#pragma unroll
    for (int kk = 0; kk < 4; kk++)
        LDSM_X4(qa[kk][0], qa[kk][1], qa[kk][2], qa[kk][3], sQb + qa_off + kk * 32);

#pragma unroll 1
    for (int t = 0; t < 8; t++) {
        if (t > 0) {
            cp_wait<0>();
            __syncthreads();
        }
        if (t < 7) {
            __half* dK = sK + ((t + 1) & 1) * (128 * 72);
            const __half* ksrc = kb + (long)(t + 1) * 128 * EE;
#pragma unroll
            for (int i = 0; i < 8; i++) {
                int idx = tid + i * 128;
                int r = idx >> 3, c8 = idx & 7;
                cpa16(stou(dK + r * 72 + c8 * 8), ksrc + (long)r * EE + c8 * 8);
            }
            __half* dV = sV + ((t + 1) & 1) * (72 * 136);
#pragma unroll
            for (int i = 0; i < 8; i++) {
                int idx = tid + i * 128;
                int r = idx >> 4, c16 = idx & 15;
                cpa16(stou(dV + r * 136 + c16 * 8), vb + (long)r * L2 + (t + 1) * 128 + c16 * 8);
            }
            cp_commit();
        }

        const uint32_t kbase = sKb0 + (uint32_t)((t & 1) * (128 * 72 * 2));
        const uint32_t vbase = sVb0 + (uint32_t)((t & 1) * (72 * 136 * 2));

        // ---- S = Q K^T ----
        float4 accS[16];
#pragma unroll
        for (int nt = 0; nt < 16; nt++) accS[nt] = make_float4(0.f, 0.f, 0.f, 0.f);

#pragma unroll
        for (int kk = 0; kk < 4; kk++) {
#pragma unroll
            for (int jp = 0; jp < 8; jp++) {
                uint32_t b0, b1, b2, b3;
                LDSM_X4(b0, b1, b2, b3, kbase + jp * (16 * 72 * 2) + kk * 32 + kb_off);
                mma_f16(accS[2 * jp],     qa[kk][0], qa[kk][1], qa[kk][2], qa[kk][3], b0, b1);
                mma_f16(accS[2 * jp + 1], qa[kk][0], qa[kk][1], qa[kk][2], qa[kk][3], b2, b3);
            }
        }

        // ---- P = exp2(S) directly (max-free; range bounded by construction) ----
        uint32_t pLo[16], pHi[16];
#pragma unroll
        for (int nt = 0; nt < 16; nt++) {
            pLo[nt] = ex2h2(h2pack(accS[nt].x, accS[nt].y));
            pHi[nt] = ex2h2(h2pack(accS[nt].z, accS[nt].w));
        }

        // ---- O += P V^T (and row-sum via ones tile) ----
#pragma unroll
        for (int kk = 0; kk < 8; kk++) {
            uint32_t a0 = pLo[2 * kk], a1 = pHi[2 * kk];
            uint32_t a2 = pLo[2 * kk + 1], a3 = pHi[2 * kk + 1];
#pragma unroll
            for (int jp = 0; jp < 4; jp++) {
                uint32_t b0, b1, b2, b3;
                LDSM_X4(b0, b1, b2, b3, vbase + jp * (16 * 136 * 2) + kk * 32 + vb_off);
                mma_f16(accO[2 * jp],     a0, a1, a2, a3, b0, b1);
                mma_f16(accO[2 * jp + 1], a0, a1, a2, a3, b2, b3);
            }
            uint32_t c0, c1;
            LDSM_X2(c0, c1, vbase + kk * 32 + v2_off);
            mma_f16(accO[8], a0, a1, a2, a3, c0, c1);
        }
    }

    // ---- epilogue: O[e][l] = accO / rowsum ----
    float s_lo = __shfl_sync(0xffffffffu, accO[8].x, lane & ~3);
    float s_hi = __shfl_sync(0xffffffffu, accO[8].z, lane & ~3);
    float i_lo = 1.0f / s_lo;
    float i_hi = 1.0f / s_hi;
#pragma unroll
    for (int nt = 0; nt < 8; nt++) {
        int e = nt * 8 + 2 * tig;
        ob[(long)e * LF + row_lo]       = __float2half_rn(accO[nt].x * i_lo);
        ob[(long)(e + 1) * LF + row_lo] = __float2half_rn(accO[nt].y * i_lo);
        ob[(long)e * LF + row_hi]       = __float2half_rn(accO[nt].z * i_hi);
        ob[(long)(e + 1) * LF + row_hi] = __float2half_rn(accO[nt].w * i_hi);
    }
}

// ---------------- launch ----------------
extern "C" void kernel_launch(void* const* d_in, const int* in_sizes, int n_in,
                              void* d_out, int out_size) {
    const float* x  = (const float*)d_in[0];
    const float* Wq = (const float*)d_in[1];  const float* bq = (const float*)d_in[2];
    const float* Wk = (const float*)d_in[3];  const float* bk = (const float*)d_in[4];
    const float* Wv = (const float*)d_in[5];  const float* bv = (const float*)d_in[6];
    const float* Wo = (const float*)d_in[7];  const float* bo = (const float*)d_in[8];
    const float* Wa = (const float*)d_in[9];
    const float* g1 = (const float*)d_in[10]; const float* b1 = (const float*)d_in[11];
    const float* m1 = (const float*)d_in[12]; const float* v1 = (const float*)d_in[13];
    const float* g2 = (const float*)d_in[14]; const float* b2 = (const float*)d_in[15];
    const float* m2 = (const float*)d_in[16]; const float* v2 = (const float*)d_in[17];
    float* out = (float*)d_out;
    (void)in_sizes; (void)n_in; (void)out_size;

    float *pS, *pT;
    __half *pXh, *pXaggh, *pXah, *pQh, *pKh, *pVh, *pOh;
    __half *pWqh, *pWkh, *pWvh, *pWoh, *pWah;
    cudaGetSymbolAddress((void**)&pXh,    d_xh);
    cudaGetSymbolAddress((void**)&pXaggh, d_xaggh);
    cudaGetSymbolAddress((void**)&pXah,   d_xah);
    cudaGetSymbolAddress((void**)&pQh,    d_qh);
    cudaGetSymbolAddress((void**)&pKh,    d_kh);
    cudaGetSymbolAddress((void**)&pVh,    d_vh);
    cudaGetSymbolAddress((void**)&pOh,    d_oh);
    cudaGetSymbolAddress((void**)&pWqh,   d_wqh);
    cudaGetSymbolAddress((void**)&pWkh,   d_wkh);
    cudaGetSymbolAddress((void**)&pWvh,   d_wvh);
    cudaGetSymbolAddress((void**)&pWoh,   d_woh);
    cudaGetSymbolAddress((void**)&pWah,   d_wah);
    cudaGetSymbolAddress((void**)&pS,     d_bns);
    cudaGetSymbolAddress((void**)&pT,     d_bnt);

    cudaFuncSetAttribute(flash_kernel, cudaFuncAttributeMaxDynamicSharedMemorySize,
                         FLASH_SMEM_BYTES);
    cudaFuncSetAttribute(hgemm<128, 4, 0>, cudaFuncAttributeMaxDynamicSharedMemorySize,
                         HGEMM128_SMEM);
    cudaFuncSetAttribute(hgemm<128, 4, 1>, cudaFuncAttributeMaxDynamicSharedMemorySize,
                         HGEMM128_SMEM);
    cudaFuncSetAttribute(hgemm<64, 2, 2>, cudaFuncAttributeMaxDynamicSharedMemorySize,
                         HGEMM64_SMEM);
    cudaFuncSetAttribute(hgemm<64, 2, 3>, cudaFuncAttributeMaxDynamicSharedMemorySize,
                         HGEMM64_SMEM);

    const float QSCALE = 0.125f * 1.44269504089f;  // fold 1/sqrt(E) and log2e into Q

    // 1) fused prep: x->fp16 + pooling, weights->fp16, BN fold
    prep_kernel<<<NB * CCH + 160 + 1, 256>>>(x, Wq, Wk, Wv, Wo, Wa,
                                             g1, b1, m1, v1, g2, b2, m2, v2);

    // 2) Q = fp16[l][e] of log2e*0.125*(Wq x + bq)
    hgemm<128, 4, 1><<<dim3(LF / 128, CCH / 128, NB), 256, HGEMM128_SMEM>>>(
        pWqh, nullptr, pXh, nullptr, pQh, nullptr, CCH, LF, LF,
        0, (long)CCH * LF, 0, QSCALE, QSCALE, nullptr, bq, nullptr);

    // 3) xa = BN2(BN1(Wa @ xagg))  fp16 direct
    hgemm<64, 2, 2><<<dim3(L2 / 128, CCH / 64, NB), 256, HGEMM64_SMEM>>>(
        pWah, nullptr, pXaggh, nullptr, pXah, nullptr, CCH, L2, L2,
        0, (long)CCH * L2, 0, 1.0f, 1.0f, pS, pT, nullptr);

    // 4) K (transposed) and V (direct) in ONE dual launch
    hgemm<64, 2, 3><<<dim3(L2 / 128, CCH / 64, NB * 2), 256, HGEMM64_SMEM>>>(
        pWkh, pWvh, pXah, nullptr, pKh, pVh, CCH, L2, L2,
        0, (long)CCH * L2, 0, 1.0f, 1.0f, nullptr, bk, bv);

    // 5) fused attention: 64-query CTAs, 2 per SM, max-free softmax
    flash_kernel<<<dim3(LF / 64, NB * HH), 128, FLASH_SMEM_BYTES>>>(pQh, pKh, pVh, pOh);

    // 6) out = Wo @ o + bo  (fp32 out)
    hgemm<128, 4, 0><<<dim3(LF / 128, CCH / 128, NB), 256, HGEMM128_SMEM>>>(
        pWoh, nullptr, pOh, out, nullptr, nullptr, CCH, LF, LF,
        0, (long)CCH * LF, (long)CCH * LF, 1.0f, 1.0f, nullptr, bo, nullptr);
}

// round 16
// speedup vs baseline: 1.4768x; 1.0236x over previous
#include <cuda_runtime.h>
#include <cuda_fp16.h>
#include <cstdint>

// Problem constants
#define NB  4
#define CCH 256
#define LF  4096
#define L2  1024
#define HH  4
#define EE  64

// ---------------- device scratch (static; no cudaMalloc) ----------------
__device__ __half d_xh   [NB * CCH * LF];
__device__ __half d_xaggh[NB * CCH * L2];
__device__ __half d_xah  [NB * CCH * L2];
__device__ __half d_qh   [NB * HH * LF * EE];  // [n][h][l][e], log2e*0.125*(Wq x + bq)
__device__ __half d_kh   [NB * HH * L2 * EE];  // [n][h][m][e]
__device__ __half d_vh   [NB * HH * EE * L2];  // [n][h][e][m]
__device__ __half d_oh   [NB * CCH * LF];
__device__ __half d_wqh[CCH * CCH], d_wkh[CCH * CCH], d_wvh[CCH * CCH];
__device__ __half d_woh[CCH * CCH], d_wah[CCH * CCH];
__device__ float  d_bns[CCH];
__device__ float  d_bnt[CCH];

// ---------------- fused prep: x->fp16 + pooling, weights->fp16, BN fold ----------------
__global__ void prep_kernel(const float* __restrict__ x,
                            const float* __restrict__ wq, const float* __restrict__ wk,
                            const float* __restrict__ wv, const float* __restrict__ wo,
                            const float* __restrict__ wa,
                            const float* __restrict__ g1, const float* __restrict__ b1,
                            const float* __restrict__ m1, const float* __restrict__ v1,
                            const float* __restrict__ g2, const float* __restrict__ b2,
                            const float* __restrict__ m2, const float* __restrict__ v2) {
    int b = blockIdx.x;
    int tid = threadIdx.x;
    if (b < NB * CCH) {
        const float4* xr = reinterpret_cast<const float4*>(x + (long)b * LF);
        __half2* xo = reinterpret_cast<__half2*>(d_xh) + (long)b * (LF / 2);
        __half*  ao = d_xaggh + (long)b * L2;
#pragma unroll
        for (int k = 0; k < 4; k++) {
            int j = tid + k * 256;
            float4 t = xr[j];
            xo[2 * j]     = __floats2half2_rn(t.x, t.y);
            xo[2 * j + 1] = __floats2half2_rn(t.z, t.w);
            float mx = fmaxf(fmaxf(t.x, t.y), fmaxf(t.z, t.w));
            ao[j] = __float2half_rn(0.25f * (t.x + t.y + t.z + t.w) + mx);
        }
    } else if (b < NB * CCH + 160) {
        const float* src[5] = {wq, wk, wv, wo, wa};
        __half* dst[5] = {d_wqh, d_wkh, d_wvh, d_woh, d_wah};
#pragma unroll
        for (int k = 0; k < 2; k++) {
            int idx = (b - NB * CCH) * 512 + k * 256 + tid;
            int m = idx >> 14;
            int j = idx & 16383;
            float4 t = reinterpret_cast<const float4*>(src[m])[j];
            __half2* o = reinterpret_cast<__half2*>(dst[m]);
            o[2 * j]     = __floats2half2_rn(t.x, t.y);
            o[2 * j + 1] = __floats2half2_rn(t.z, t.w);
        }
    } else {
        int c = tid;
        float i1 = g1[c] * rsqrtf(v1[c] + 1e-5f);
        float c1 = b1[c] - m1[c] * i1;
        float i2 = g2[c] * rsqrtf(v2[c] + 1e-5f);
        float c2 = b2[c] - m2[c] * i2;
        d_bns[c] = i1 * i2;
        d_bnt[c] = c1 * i2 + c2;
    }
}

// ---------------- helpers ----------------
__device__ __forceinline__ void mma_f16(float4& c, uint32_t a0, uint32_t a1, uint32_t a2,
                                        uint32_t a3, uint32_t b0, uint32_t b1) {
    asm volatile(
        "mma.sync.aligned.m16n8k16.row.col.f32.f16.f16.f32 "
        "{%0,%1,%2,%3}, {%4,%5,%6,%7}, {%8,%9}, {%0,%1,%2,%3};\n"
        : "+f"(c.x), "+f"(c.y), "+f"(c.z), "+f"(c.w)
        : "r"(a0), "r"(a1), "r"(a2), "r"(a3), "r"(b0), "r"(b1));
}
__device__ __forceinline__ uint32_t h2pack(float a, float b) {
    __half2 h = __floats2half2_rn(a, b);
    return *reinterpret_cast<uint32_t*>(&h);
}
__device__ __forceinline__ uint32_t ex2h2(uint32_t in) {
    uint32_t r;
    asm("ex2.approx.f16x2 %0, %1;" : "=r"(r) : "r"(in));
    return r;
}
__device__ __forceinline__ uint32_t stou(const void* p) {
    return (uint32_t)__cvta_generic_to_shared(p);
}
__device__ __forceinline__ void cpa16(uint32_t dst, const void* src) {
    asm volatile("cp.async.cg.shared.global [%0], [%1], 16;\n" :: "r"(dst), "l"(src));
}
__device__ __forceinline__ void cpa16ca(uint32_t dst, const void* src) {
    asm volatile("cp.async.ca.shared.global [%0], [%1], 16;\n" :: "r"(dst), "l"(src));
}
__device__ __forceinline__ void cp_commit() { asm volatile("cp.async.commit_group;\n"); }
template <int N> __device__ __forceinline__ void cp_wait() {
    asm volatile("cp.async.wait_group %0;\n" :: "n"(N));
}
#define LDSM_X4(r0, r1, r2, r3, addr) \
    asm volatile("ldmatrix.sync.aligned.m8n8.x4.shared.b16 {%0,%1,%2,%3}, [%4];" \
                 : "=r"(r0), "=r"(r1), "=r"(r2), "=r"(r3) : "r"(addr))
#define LDSM_X4_T(r0, r1, r2, r3, addr) \
    asm volatile("ldmatrix.sync.aligned.m8n8.x4.trans.shared.b16 {%0,%1,%2,%3}, [%4];" \
                 : "=r"(r0), "=r"(r1), "=r"(r2), "=r"(r3) : "r"(addr))
#define LDSM_X2(r0, r1, addr) \
    asm volatile("ldmatrix.sync.aligned.m8n8.x2.shared.b16 {%0,%1}, [%2];" \
                 : "=r"(r0), "=r"(r1) : "r"(addr))

// ---------------- fp16 3-stage GEMM ----------------
// acc = sum_k A[m][k]*B[k][n]  (A fp16 [M][K] lda, B fp16 [K][N] ldb, K=256)
// OMODE 0: Y fp32.  OMODE 1: fp16 transposed per 64-row head.
// OMODE 3: DUAL K/V (z even: K transposed; z odd: V direct).
// OMODE 4: MERGED Q+xa (z&1==0: Q -> Yh transposed, ldb/ldy=LF; z&1==1: xa -> Yh2 direct,
//          B=B2, ldb/ldy=L2, alpha=beta=1, rs/rb2 epilogue; blockIdx.x>=8 exits).
template <int BM, int TMt, int OMODE>
__global__ __launch_bounds__(256, 2) void hgemm(
    const __half* __restrict__ A, const __half* __restrict__ A2,
    const __half* __restrict__ B, const __half* __restrict__ B2,
    float* __restrict__ Y, __half* __restrict__ Yh, __half* __restrict__ Yh2,
    int lda, int ldb, int ldy,
    long aB, long bB, long yB, float alpha, float beta,
    const float* __restrict__ rs,
    const float* __restrict__ rb, const float* __restrict__ rb2)
{
    extern __shared__ __half smH[];
    __half* sA = smH;                   // [3][BM][40]
    __half* sB = smH + 3 * BM * 40;     // [3][32][136]

    int sel = 0;
    long zb;
    int ldb_r = ldb, ldy_r = ldy;
    long bB_r = bB;
    if (OMODE == 3) {
        sel = blockIdx.z & 1;
        zb  = blockIdx.z >> 1;
        if (sel) { A = A2; rb = rb2; }
    } else if (OMODE == 4) {
        sel = blockIdx.z & 1;
        zb  = blockIdx.z >> 1;
        if (sel) {
            if (blockIdx.x >= L2 / 128) return;
            A = A2; B = B2; rb = rb2;
            ldb_r = L2; ldy_r = L2;
            bB_r = (long)CCH * L2;
            alpha = 1.0f; beta = 1.0f;
        } else {
            rs = nullptr;
        }
    } else {
        zb = blockIdx.z;
    }
    A += zb * aB;
    B += zb * bB_r;

    const int tid  = threadIdx.x;
    const int lane = tid & 31;
    const int wid  = tid >> 5;
    const int wm   = wid >> 2;
    const int wn   = wid & 3;
    const int g    = lane >> 2;
    const int tig  = lane & 3;
    const int m0   = blockIdx.y * BM;
    const int n0   = blockIdx.x * 128;

    const uint32_t a_off = ((lane & 15) * 40 + (lane >> 4) * 8) * 2;
    const uint32_t b_off = ((lane & 15) * 136 + (lane >> 4) * 8) * 2;

    float4 acc[TMt][4];
#pragma unroll
    for (int i = 0; i < TMt; i++)
#pragma unroll
        for (int j = 0; j < 4; j++) acc[i][j] = make_float4(0.f, 0.f, 0.f, 0.f);

    auto prefetch = [&](int t, int buf) {
        __half* dA = sA + buf * BM * 40;
        __half* dB = sB + buf * 32 * 136;
#pragma unroll
        for (int i = tid; i < BM * 4; i += 256) {
            int r = i >> 2, c = (i & 3) * 8;
            cpa16(stou(dA + r * 40 + c), A + (long)(m0 + r) * lda + t * 32 + c);
        }
#pragma unroll
        for (int i = tid; i < 512; i += 256) {
            int r = i >> 4, c = (i & 15) * 8;
            cpa16(stou(dB + r * 136 + c), B + (long)(t * 32 + r) * ldb_r + n0 + c);
        }
    };

    prefetch(0, 0); cp_commit();
    prefetch(1, 1); cp_commit();

    for (int t = 0; t < 8; t++) {
        if (t < 7) cp_wait<1>(); else cp_wait<0>();
        __syncthreads();
        if (t + 2 < 8) { prefetch(t + 2, (t + 2) % 3); cp_commit(); }

        const uint32_t aBase = stou(sA) + (uint32_t)((t % 3) * BM * 40 * 2);
        const uint32_t bBase = stou(sB) + (uint32_t)((t % 3) * 32 * 136 * 2);

#pragma unroll
        for (int s = 0; s < 2; s++) {
            uint32_t a[TMt][4];
#pragma unroll
            for (int mt = 0; mt < TMt; mt++)
                LDSM_X4(a[mt][0], a[mt][1], a[mt][2], a[mt][3],
                        aBase + (uint32_t)(((wm * TMt * 16 + mt * 16) * 40 + s * 16) * 2) + a_off);
            uint32_t b[2][4];
#pragma unroll
            for (int j = 0; j < 2; j++)
                LDSM_X4_T(b[j][0], b[j][1], b[j][2], b[j][3],
                          bBase + (uint32_t)((s * 16 * 136 + wn * 32 + j * 16) * 2) + b_off);
#pragma unroll
            for (int mt = 0; mt < TMt; mt++)
#pragma unroll
                for (int nt = 0; nt < 4; nt++)
                    mma_f16(acc[mt][nt], a[mt][0], a[mt][1], a[mt][2], a[mt][3],
                            b[nt >> 1][(nt & 1) * 2], b[nt >> 1][(nt & 1) * 2 + 1]);
        }
    }

    const bool kpath = (OMODE == 1) || (OMODE == 3 && sel == 0) || (OMODE == 4 && sel == 0);
    if (kpath) {
        __syncthreads();
        __half* sT = smH;
        const int st = BM + 2;
#pragma unroll
        for (int mt = 0; mt < TMt; mt++) {
            int rl = wm * (TMt * 16) + mt * 16 + g;
            int r = m0 + rl;
            float t0 = beta * (rb ? rb[r] : 0.0f);
            float t1 = beta * (rb ? rb[r + 8] : 0.0f);
#pragma unroll
            for (int nt = 0; nt < 4; nt++) {
                int c = wn * 32 + nt * 8 + 2 * tig;
                sT[c * st + rl]           = __float2half_rn(acc[mt][nt].x * alpha + t0);
                sT[(c + 1) * st + rl]     = __float2half_rn(acc[mt][nt].y * alpha + t0);
                sT[c * st + rl + 8]       = __float2half_rn(acc[mt][nt].z * alpha + t1);
                sT[(c + 1) * st + rl + 8] = __float2half_rn(acc[mt][nt].w * alpha + t1);
            }
        }
        __syncthreads();
        uint32_t* Y32 = reinterpret_cast<uint32_t*>(Yh);
        for (int i = tid; i < 128 * (BM / 2); i += 256) {
            int lc = i / (BM / 2);
            int rp = (i % (BM / 2)) * 2;
            uint32_t v = *reinterpret_cast<uint32_t*>(&sT[lc * st + rp]);
            int r = m0 + rp;
            int h = r >> 6, e = r & 63;
            Y32[((zb * HH + h) * (long)ldy_r + n0 + lc) * 32 + (e >> 1)] = v;
        }
    } else {
#pragma unroll
        for (int mt = 0; mt < TMt; mt++) {
            int r = m0 + wm * (TMt * 16) + mt * 16 + g;
            float s0 = alpha * (rs ? rs[r] : 1.0f),     t0 = beta * (rb ? rb[r] : 0.0f);
            float s1 = alpha * (rs ? rs[r + 8] : 1.0f), t1 = beta * (rb ? rb[r + 8] : 0.0f);
#pragma unroll
            for (int nt = 0; nt < 4; nt++) {
                int c = n0 + wn * 32 + nt * 8 + 2 * tig;
                float y00 = acc[mt][nt].x * s0 + t0, y01 = acc[mt][nt].y * s0 + t0;
                float y10 = acc[mt][nt].z * s1 + t1, y11 = acc[mt][nt].w * s1 + t1;
                if (OMODE == 3 || OMODE == 4) {
                    uint32_t* Y32 = reinterpret_cast<uint32_t*>(Yh2);
                    Y32[((zb * CCH + r) * (long)ldy_r + c) >> 1]     = h2pack(y00, y01);
                    Y32[((zb * CCH + r + 8) * (long)ldy_r + c) >> 1] = h2pack(y10, y11);
                } else {
                    float* Yb = Y + zb * yB;
                    *reinterpret_cast<float2*>(Yb + (long)r * ldy_r + c) = make_float2(y00, y01);
                    *reinterpret_cast<float2*>(Yb + (long)(r + 8) * ldy_r + c) = make_float2(y10, y11);
                }
            }
        }
    }
}

#define HGEMM128_SMEM (3 * (128 * 40 + 32 * 136) * 2)
#define HGEMM64_SMEM  (3 * (64 * 40 + 32 * 136) * 2)

// ---------------- fused flash attention: 128 threads, 2 CTAs/SM, max-free softmax ----------------
// cp.async.ca for Q/K/V: co-resident CTAs mostly share (n,h) -> L1 reuse halves L2 pull.
#define SQH 0
#define SKH (64 * 72)
#define SVH (SKH + 2 * 128 * 72)
#define FLASH_SMEM_BYTES ((SVH + 2 * 72 * 136) * 2)   // 85,248 B

__global__ __launch_bounds__(128, 2) void flash_kernel(
    const __half* __restrict__ Qh, const __half* __restrict__ Kh,
    const __half* __restrict__ Vh, __half* __restrict__ O)
{
    extern __shared__ __half smh[];
    __half* sQ = smh + SQH;
    __half* sK = smh + SKH;
    __half* sV = smh + SVH;

    const int tid  = threadIdx.x;
    const int lane = tid & 31;
    const int w    = tid >> 5;
    const int g    = lane >> 2;
    const int tig  = lane & 3;

    const int l0 = blockIdx.x * 64;
    const int nh = blockIdx.y;
    const int n  = nh >> 2, h = nh & 3;
    const __half* qb = Qh + (((long)(n * HH + h)) * LF + l0) * EE;
    const __half* kb = Kh + ((long)(n * HH + h)) * L2 * EE;
    const __half* vb = Vh + ((long)(n * HH + h)) * EE * L2;
    __half*       ob = O + ((long)n * CCH + h * 64) * LF + l0;

    const int row_lo = w * 16 + g;
    const int row_hi = row_lo + 8;

    const int qrow = lane & 7;
    const int sel  = lane >> 3;
    const uint32_t sQb = stou(sQ), sKb0 = stou(sK), sVb0 = stou(sV);
    const uint32_t qa_off = ((w * 16 + (lane & 15)) * 72 + (lane >> 4) * 8) * 2;
    const uint32_t kb_off = (((sel >> 1) * 8 + qrow) * 72 + (sel & 1) * 8) * 2;
    const uint32_t vb_off = (((sel >> 1) * 8 + qrow) * 136 + (sel & 1) * 8) * 2;
    const uint32_t v2_off = ((64 + qrow) * 136 + ((lane >> 3) & 1) * 8) * 2;

    // prologue: Q (group 0); K0+V0 (group 1)
#pragma unroll
    for (int i = 0; i < 4; i++) {
        int idx = tid + i * 128;
        int r = idx >> 3, c8 = idx & 7;
        cpa16ca(stou(sQ + r * 72 + c8 * 8), qb + (long)r * EE + c8 * 8);
    }
    cp_commit();
#pragma unroll
    for (int i = 0; i < 8; i++) {
        int idx = tid + i * 128;
        int r = idx >> 3, c8 = idx & 7;
        cpa16ca(stou(sK + r * 72 + c8 * 8), kb + (long)r * EE + c8 * 8);
    }
#pragma unroll
    for (int i = 0; i < 8; i++) {
        int idx = tid + i * 128;
        int r = idx >> 4, c16 = idx & 15;
        cpa16ca(stou(sV + r * 136 + c16 * 8), vb + (long)r * L2 + c16 * 8);
    }
    cp_commit();

    // ones/zeros rows 64-71 of both V buffers
    {
        uint32_t* sV32w = reinterpret_cast<uint32_t*>(sV);
        for (int i = tid; i < 2 * 8 * 68; i += 128) {
            int buf = i / (8 * 68);
            int rem = i % (8 * 68);
            int r = rem / 68, c = rem % 68;
            sV32w[buf * (72 * 68) + (64 + r) * 68 + c] = (r == 0) ? 0x3C003C00u : 0u;
        }
    }

    float4 accO[9];
#pragma unroll
    for (int nt = 0; nt < 9; nt++) accO[nt] = make_float4(0.f, 0.f, 0.f, 0.f);

    cp_wait<0>();
    __syncthreads();

    uint32_t qa[4][4];
#pragma unroll
    for (int kk = 0; kk < 4; kk++)
        LDSM_X4(qa[kk][0], qa[kk][1], qa[kk][2], qa[kk][3], sQb + qa_off + kk * 32);

#pragma unroll 1
    for (int t = 0; t < 8; t++) {
        if (t > 0) {
            cp_wait<0>();
            __syncthreads();
        }
        if (t < 7) {
            __half* dK = sK + ((t + 1) & 1) * (128 * 72);
            const __half* ksrc = kb + (long)(t + 1) * 128 * EE;
#pragma unroll
            for (int i = 0; i < 8; i++) {
                int idx = tid + i * 128;
                int r = idx >> 3, c8 = idx & 7;
                cpa16ca(stou(dK + r * 72 + c8 * 8), ksrc + (long)r * EE + c8 * 8);
            }
            __half* dV = sV + ((t + 1) & 1) * (72 * 136);
#pragma unroll
            for (int i = 0; i < 8; i++) {
                int idx = tid + i * 128;
                int r = idx >> 4, c16 = idx & 15;
                cpa16ca(stou(dV + r * 136 + c16 * 8), vb + (long)r * L2 + (t + 1) * 128 + c16 * 8);
            }
            cp_commit();
        }

        const uint32_t kbase = sKb0 + (uint32_t)((t & 1) * (128 * 72 * 2));
        const uint32_t vbase = sVb0 + (uint32_t)((t & 1) * (72 * 136 * 2));

        // ---- S = Q K^T ----
        float4 accS[16];
#pragma unroll
        for (int nt = 0; nt < 16; nt++) accS[nt] = make_float4(0.f, 0.f, 0.f, 0.f);

#pragma unroll
        for (int kk = 0; kk < 4; kk++) {
#pragma unroll
            for (int jp = 0; jp < 8; jp++) {
                uint32_t b0, b1, b2, b3;
                LDSM_X4(b0, b1, b2, b3, kbase + jp * (16 * 72 * 2) + kk * 32 + kb_off);
                mma_f16(accS[2 * jp],     qa[kk][0], qa[kk][1], qa[kk][2], qa[kk][3], b0, b1);
                mma_f16(accS[2 * jp + 1], qa[kk][0], qa[kk][1], qa[kk][2], qa[kk][3], b2, b3);
            }
        }

        // ---- P = exp2(S) directly (max-free; range bounded by construction) ----
        uint32_t pLo[16], pHi[16];
#pragma unroll
        for (int nt = 0; nt < 16; nt++) {
            pLo[nt] = ex2h2(h2pack(accS[nt].x, accS[nt].y));
            pHi[nt] = ex2h2(h2pack(accS[nt].z, accS[nt].w));
        }

        // ---- O += P V^T (and row-sum via ones tile) ----
#pragma unroll
        for (int kk = 0; kk < 8; kk++) {
            uint32_t a0 = pLo[2 * kk], a1 = pHi[2 * kk];
            uint32_t a2 = pLo[2 * kk + 1], a3 = pHi[2 * kk + 1];
#pragma unroll
            for (int jp = 0; jp < 4; jp++) {
                uint32_t b0, b1, b2, b3;
                LDSM_X4(b0, b1, b2, b3, vbase + jp * (16 * 136 * 2) + kk * 32 + vb_off);
                mma_f16(accO[2 * jp],     a0, a1, a2, a3, b0, b1);
                mma_f16(accO[2 * jp + 1], a0, a1, a2, a3, b2, b3);
            }
            uint32_t c0, c1;
            LDSM_X2(c0, c1, vbase + kk * 32 + v2_off);
            mma_f16(accO[8], a0, a1, a2, a3, c0, c1);
        }
    }

    // ---- epilogue: O[e][l] = accO / rowsum ----
    float s_lo = __shfl_sync(0xffffffffu, accO[8].x, lane & ~3);
    float s_hi = __shfl_sync(0xffffffffu, accO[8].z, lane & ~3);
    float i_lo = 1.0f / s_lo;
    float i_hi = 1.0f / s_hi;
#pragma unroll
    for (int nt = 0; nt < 8; nt++) {
        int e = nt * 8 + 2 * tig;
        ob[(long)e * LF + row_lo]       = __float2half_rn(accO[nt].x * i_lo);
        ob[(long)(e + 1) * LF + row_lo] = __float2half_rn(accO[nt].y * i_lo);
        ob[(long)e * LF + row_hi]       = __float2half_rn(accO[nt].z * i_hi);
        ob[(long)(e + 1) * LF + row_hi] = __float2half_rn(accO[nt].w * i_hi);
    }
}

// ---------------- launch ----------------
extern "C" void kernel_launch(void* const* d_in, const int* in_sizes, int n_in,
                              void* d_out, int out_size) {
    const float* x  = (const float*)d_in[0];
    const float* Wq = (const float*)d_in[1];  const float* bq = (const float*)d_in[2];
    const float* Wk = (const float*)d_in[3];  const float* bk = (const float*)d_in[4];
    const float* Wv = (const float*)d_in[5];  const float* bv = (const float*)d_in[6];
    const float* Wo = (const float*)d_in[7];  const float* bo = (const float*)d_in[8];
    const float* Wa = (const float*)d_in[9];
    const float* g1 = (const float*)d_in[10]; const float* b1 = (const float*)d_in[11];
    const float* m1 = (const float*)d_in[12]; const float* v1 = (const float*)d_in[13];
    const float* g2 = (const float*)d_in[14]; const float* b2 = (const float*)d_in[15];
    const float* m2 = (const float*)d_in[16]; const float* v2 = (const float*)d_in[17];
    float* out = (float*)d_out;
    (void)in_sizes; (void)n_in; (void)out_size;

    float *pS, *pT;
    __half *pXh, *pXaggh, *pXah, *pQh, *pKh, *pVh, *pOh;
    __half *pWqh, *pWkh, *pWvh, *pWoh, *pWah;
    cudaGetSymbolAddress((void**)&pXh,    d_xh);
    cudaGetSymbolAddress((void**)&pXaggh, d_xaggh);
    cudaGetSymbolAddress((void**)&pXah,   d_xah);
    cudaGetSymbolAddress((void**)&pQh,    d_qh);
    cudaGetSymbolAddress((void**)&pKh,    d_kh);
    cudaGetSymbolAddress((void**)&pVh,    d_vh);
    cudaGetSymbolAddress((void**)&pOh,    d_oh);
    cudaGetSymbolAddress((void**)&pWqh,   d_wqh);
    cudaGetSymbolAddress((void**)&pWkh,   d_wkh);
    cudaGetSymbolAddress((void**)&pWvh,   d_wvh);
    cudaGetSymbolAddress((void**)&pWoh,   d_woh);
    cudaGetSymbolAddress((void**)&pWah,   d_wah);
    cudaGetSymbolAddress((void**)&pS,     d_bns);
    cudaGetSymbolAddress((void**)&pT,     d_bnt);

    cudaFuncSetAttribute(flash_kernel, cudaFuncAttributeMaxDynamicSharedMemorySize,
                         FLASH_SMEM_BYTES);
    cudaFuncSetAttribute(hgemm<128, 4, 0>, cudaFuncAttributeMaxDynamicSharedMemorySize,
                         HGEMM128_SMEM);
    cudaFuncSetAttribute(hgemm<128, 4, 4>, cudaFuncAttributeMaxDynamicSharedMemorySize,
                         HGEMM128_SMEM);
    cudaFuncSetAttribute(hgemm<64, 2, 3>, cudaFuncAttributeMaxDynamicSharedMemorySize,
                         HGEMM64_SMEM);

    const float QSCALE = 0.125f * 1.44269504089f;  // fold 1/sqrt(E) and log2e into Q

    // 1) fused prep: x->fp16 + pooling, weights->fp16, BN fold
    prep_kernel<<<NB * CCH + 160 + 1, 256>>>(x, Wq, Wk, Wv, Wo, Wa,
                                             g1, b1, m1, v1, g2, b2, m2, v2);

    // 2) MERGED: Q = fp16[l][e] of log2e*0.125*(Wq x + bq)  AND  xa = BN2(BN1(Wa xagg))
    hgemm<128, 4, 4><<<dim3(LF / 128, CCH / 128, NB * 2), 256, HGEMM128_SMEM>>>(
        pWqh, pWah, pXh, pXaggh, nullptr, pQh, pXah, CCH, LF, LF,
        0, (long)CCH * LF, 0, QSCALE, QSCALE, pS, bq, pT);

    // 3) K (transposed) and V (direct) in ONE dual launch
    hgemm<64, 2, 3><<<dim3(L2 / 128, CCH / 64, NB * 2), 256, HGEMM64_SMEM>>>(
        pWkh, pWvh, pXah, nullptr, nullptr, pKh, pVh, CCH, L2, L2,
        0, (long)CCH * L2, 0, 1.0f, 1.0f, nullptr, bk, bv);

    // 4) fused attention: 64-query CTAs, 2 per SM, max-free softmax, .ca K/V loads
    flash_kernel<<<dim3(LF / 64, NB * HH), 128, FLASH_SMEM_BYTES>>>(pQh, pKh, pVh, pOh);

    // 5) out = Wo @ o + bo  (fp32 out)
    hgemm<128, 4, 0><<<dim3(LF / 128, CCH / 128, NB), 256, HGEMM128_SMEM>>>(
        pWoh, nullptr, pOh, nullptr, out, nullptr, nullptr, CCH, LF, LF,
        0, (long)CCH * LF, (long)CCH * LF, 1.0f, 1.0f, nullptr, bo, nullptr);
}